// round 1
// baseline (speedup 1.0000x reference)
#include <cuda_runtime.h>
#include <math.h>

#define TTOK  16384      // B*S = 8*2048
#define DIM   1024
#define NEXP  4
#define RANK  16
#define ERCOL 64         // NEXP*RANK
#define LN_EPS 1e-5f

// ---------------- scratch (static device memory; no runtime alloc) ----------
__device__ float g_bufA[(size_t)TTOK * DIM];   // current activations X
__device__ float g_bufB[(size_t)TTOK * DIM];   // new_state
__device__ float g_bufC[(size_t)TTOK * DIM];   // pre-LN y
__device__ float g_H[(size_t)TTOK * ERCOL];    // masked gelu(z @ A)
__device__ int   g_maskbuf[TTOK];              // top-2 expert bitmask per token

// ---------------------------------------------------------------------------
// Main GEMM: C[M,N] = epilogue(A[M,K] @ B[K,N] + bias[N])
//   MODE 0: C = sigmoid(acc + bias) * aux * td      (gate path; aux = X)
//   MODE 1: C = acc + bias + aux                    (residual path; aux = X)
// M = TTOK, N = K = DIM. Tiles: BM=BN=128, BK=16, 256 threads, 8x8 microtile
// (split 4+4 so LDS.128 reads are conflict-free).
// ---------------------------------------------------------------------------
template<int MODE>
__global__ __launch_bounds__(256, 2) void gemm_dd(
    const float* __restrict__ A, const float* __restrict__ B,
    const float* __restrict__ bias, const float* __restrict__ aux,
    const float* __restrict__ td, float* __restrict__ C)
{
    __shared__ float As[16][132];   // transposed A tile, padded (132 % 4 == 0)
    __shared__ float Bs[16][128];

    const int m0  = blockIdx.y * 128;
    const int n0  = blockIdx.x * 128;
    const int tid = threadIdx.x;
    const int ty  = tid >> 4;     // 0..15 -> row groups
    const int tx  = tid & 15;     // 0..15 -> col groups

    float acc[8][8];
    #pragma unroll
    for (int i = 0; i < 8; i++)
        #pragma unroll
        for (int j = 0; j < 8; j++) acc[i][j] = 0.f;

    for (int k0 = 0; k0 < DIM; k0 += 16) {
        // load A tile 128x16 -> transposed As[k][m]
        #pragma unroll
        for (int t = 0; t < 2; t++) {
            int li  = tid + t * 256;
            int row = li >> 2;            // 0..127
            int kq  = (li & 3) << 2;      // 0,4,8,12
            float4 v = *(const float4*)&A[(size_t)(m0 + row) * DIM + k0 + kq];
            As[kq + 0][row] = v.x; As[kq + 1][row] = v.y;
            As[kq + 2][row] = v.z; As[kq + 3][row] = v.w;
        }
        // load B tile 16x128 -> Bs[k][n]
        #pragma unroll
        for (int t = 0; t < 2; t++) {
            int li = tid + t * 256;
            int r  = li >> 5;             // 0..15
            int c  = (li & 31) << 2;      // 0..124
            *(float4*)&Bs[r][c] = *(const float4*)&B[(size_t)(k0 + r) * DIM + n0 + c];
        }
        __syncthreads();

        #pragma unroll
        for (int k = 0; k < 16; k++) {
            float a[8], b[8];
            *(float4*)&a[0] = *(float4*)&As[k][ty * 4];
            *(float4*)&a[4] = *(float4*)&As[k][64 + ty * 4];
            *(float4*)&b[0] = *(float4*)&Bs[k][tx * 4];
            *(float4*)&b[4] = *(float4*)&Bs[k][64 + tx * 4];
            #pragma unroll
            for (int i = 0; i < 8; i++)
                #pragma unroll
                for (int j = 0; j < 8; j++)
                    acc[i][j] = fmaf(a[i], b[j], acc[i][j]);
        }
        __syncthreads();
    }

    // epilogue (two column blocks of 4, vectorized)
    const int ncol[2] = { n0 + tx * 4, n0 + 64 + tx * 4 };
    float4 bias4[2], td4[2];
    #pragma unroll
    for (int cb = 0; cb < 2; cb++) {
        bias4[cb] = *(const float4*)&bias[ncol[cb]];
        if (MODE == 0) td4[cb] = *(const float4*)&td[ncol[cb]];
    }
    #pragma unroll
    for (int i = 0; i < 8; i++) {
        int m = m0 + ((i < 4) ? (ty * 4 + i) : (64 + ty * 4 + i - 4));
        #pragma unroll
        for (int cb = 0; cb < 2; cb++) {
            float4 aux4 = *(const float4*)&aux[(size_t)m * DIM + ncol[cb]];
            float va[4] = { aux4.x, aux4.y, aux4.z, aux4.w };
            float vb[4] = { bias4[cb].x, bias4[cb].y, bias4[cb].z, bias4[cb].w };
            float vt[4];
            if (MODE == 0) { vt[0]=td4[cb].x; vt[1]=td4[cb].y; vt[2]=td4[cb].z; vt[3]=td4[cb].w; }
            float out[4];
            #pragma unroll
            for (int j = 0; j < 4; j++) {
                float v = acc[i][cb * 4 + j] + vb[j];
                if (MODE == 0) {
                    float gate = 1.0f / (1.0f + expf(-v));
                    out[j] = gate * va[j] * vt[j];
                } else {
                    out[j] = v + va[j];
                }
            }
            *(float4*)&C[(size_t)m * DIM + ncol[cb]] =
                make_float4(out[0], out[1], out[2], out[3]);
        }
    }
}

// ---------------------------------------------------------------------------
// Row LayerNorm: O[row] = (y - mu) / sqrt(var + eps) * g + beta
// One block (256 thr) per row; each thread owns one float4.
// ---------------------------------------------------------------------------
__global__ __launch_bounds__(256) void ln_kernel(
    const float* __restrict__ Y, const float* __restrict__ g,
    const float* __restrict__ beta, float* __restrict__ O)
{
    const int row = blockIdx.x;
    const int tid = threadIdx.x;
    float4 v = *(const float4*)&Y[(size_t)row * DIM + tid * 4];
    float s  = v.x + v.y + v.z + v.w;
    float ss = v.x * v.x + v.y * v.y + v.z * v.z + v.w * v.w;

    __shared__ float rs[8], rss[8];
    #pragma unroll
    for (int o = 16; o > 0; o >>= 1) {
        s  += __shfl_down_sync(0xffffffffu, s,  o);
        ss += __shfl_down_sync(0xffffffffu, ss, o);
    }
    if ((tid & 31) == 0) { rs[tid >> 5] = s; rss[tid >> 5] = ss; }
    __syncthreads();
    float ts = 0.f, tss = 0.f;
    #pragma unroll
    for (int w = 0; w < 8; w++) { ts += rs[w]; tss += rss[w]; }
    float mu   = ts * (1.0f / DIM);
    float var  = tss * (1.0f / DIM) - mu * mu;
    float rstd = rsqrtf(var + LN_EPS);

    float4 g4 = *(const float4*)&g[tid * 4];
    float4 b4 = *(const float4*)&beta[tid * 4];
    float4 o4;
    o4.x = (v.x - mu) * rstd * g4.x + b4.x;
    o4.y = (v.y - mu) * rstd * g4.y + b4.y;
    o4.z = (v.z - mu) * rstd * g4.z + b4.z;
    o4.w = (v.w - mu) * rstd * g4.w + b4.w;
    *(float4*)&O[(size_t)row * DIM + tid * 4] = o4;
}

// ---------------------------------------------------------------------------
// Gate: logits = z @ W + b -> softmax -> probs (written to out) + top-2 mask.
// One block (128 thr) per token. W is [D,4] row-major -> float4 per d.
// ---------------------------------------------------------------------------
__global__ __launch_bounds__(128) void gate_kernel(
    const float* __restrict__ Z, const float* __restrict__ W,
    const float* __restrict__ b, float* __restrict__ probs_out,
    int* __restrict__ mask_out)
{
    const int t   = blockIdx.x;
    const int tid = threadIdx.x;
    const float* z = Z + (size_t)t * DIM;
    float4 acc = make_float4(0.f, 0.f, 0.f, 0.f);
    for (int d = tid; d < DIM; d += 128) {
        float zv = z[d];
        float4 w = *(const float4*)&W[d * 4];
        acc.x = fmaf(zv, w.x, acc.x);
        acc.y = fmaf(zv, w.y, acc.y);
        acc.z = fmaf(zv, w.z, acc.z);
        acc.w = fmaf(zv, w.w, acc.w);
    }
    __shared__ float4 red[128];
    red[tid] = acc;
    __syncthreads();
    for (int s = 64; s > 0; s >>= 1) {
        if (tid < s) {
            float4 o = red[tid + s];
            red[tid].x += o.x; red[tid].y += o.y;
            red[tid].z += o.z; red[tid].w += o.w;
        }
        __syncthreads();
    }
    if (tid == 0) {
        float l[4] = { red[0].x + b[0], red[0].y + b[1],
                       red[0].z + b[2], red[0].w + b[3] };
        float mx = l[0];
        #pragma unroll
        for (int e = 1; e < 4; e++) mx = fmaxf(mx, l[e]);
        float ex[4], sum = 0.f;
        #pragma unroll
        for (int e = 0; e < 4; e++) { ex[e] = expf(l[e] - mx); sum += ex[e]; }
        float inv = 1.0f / sum;
        #pragma unroll
        for (int e = 0; e < 4; e++) probs_out[(size_t)t * 4 + e] = ex[e] * inv;
        // top-2 (ties -> lowest index, matching jax top_k)
        int i1 = 0;
        #pragma unroll
        for (int e = 1; e < 4; e++) if (l[e] > l[i1]) i1 = e;
        int i2 = -1;
        #pragma unroll
        for (int e = 0; e < 4; e++) {
            if (e == i1) continue;
            if (i2 < 0 || l[e] > l[i2]) i2 = e;
        }
        mask_out[t] = (1 << i1) | (1 << i2);
    }
}

// ---------------------------------------------------------------------------
// H = mask * gelu(Z @ Aflat)  where Aflat[d][e*16+r] = lora_A[e][d][r].
// Tiled GEMM: BM=64, BN=64 (=ERCOL), BK=16, 256 threads, 4x4 microtile.
// ---------------------------------------------------------------------------
__global__ __launch_bounds__(256) void h_kernel(
    const float* __restrict__ Z, const float* __restrict__ loraA,
    const int* __restrict__ mask, float* __restrict__ H)
{
    __shared__ float Zs[16][68];   // transposed, padded
    __shared__ float Afs[16][64];

    const int m0  = blockIdx.x * 64;
    const int tid = threadIdx.x;
    const int ty  = tid >> 4;   // 0..15 -> rows ty*4..
    const int tx  = tid & 15;   // 0..15 -> cols tx*4..

    float acc[4][4];
    #pragma unroll
    for (int i = 0; i < 4; i++)
        #pragma unroll
        for (int j = 0; j < 4; j++) acc[i][j] = 0.f;

    for (int k0 = 0; k0 < DIM; k0 += 16) {
        {   // Z tile 64x16 -> transposed
            int row = tid >> 2;            // 0..63
            int kq  = (tid & 3) << 2;
            float4 v = *(const float4*)&Z[(size_t)(m0 + row) * DIM + k0 + kq];
            Zs[kq + 0][row] = v.x; Zs[kq + 1][row] = v.y;
            Zs[kq + 2][row] = v.z; Zs[kq + 3][row] = v.w;
        }
        {   // Aflat tile 16x64
            int k  = tid >> 4;             // 0..15
            int c4 = (tid & 15) << 2;      // 0..60
            int e  = c4 >> 4;
            int r  = c4 & 15;
            float4 v = *(const float4*)&loraA[(size_t)e * DIM * RANK + (size_t)(k0 + k) * RANK + r];
            *(float4*)&Afs[k][c4] = v;
        }
        __syncthreads();
        #pragma unroll
        for (int k = 0; k < 16; k++) {
            float a[4], b[4];
            *(float4*)&a[0] = *(float4*)&Zs[k][ty * 4];
            *(float4*)&b[0] = *(float4*)&Afs[k][tx * 4];
            #pragma unroll
            for (int i = 0; i < 4; i++)
                #pragma unroll
                for (int j = 0; j < 4; j++)
                    acc[i][j] = fmaf(a[i], b[j], acc[i][j]);
        }
        __syncthreads();
    }

    #pragma unroll
    for (int i = 0; i < 4; i++) {
        int m  = m0 + ty * 4 + i;
        int mk = mask[m];
        #pragma unroll
        for (int j = 0; j < 4; j++) {
            int c = tx * 4 + j;
            int e = c >> 4;
            float x = acc[i][j];
            float h = 0.5f * x * (1.0f + erff(x * 0.70710678118654752f)); // exact gelu
            H[(size_t)m * ERCOL + c] = ((mk >> e) & 1) ? h : 0.0f;
        }
    }
}

// ---------------------------------------------------------------------------
// pred = H @ Bflat   where Bflat[e*16+r][d] = lora_B (contiguous already).
// grid (TTOK/16, DIM/256); each thread: one d column, 16 tokens.
// ---------------------------------------------------------------------------
__global__ __launch_bounds__(256) void combine_kernel(
    const float* __restrict__ H, const float* __restrict__ Bf,
    float* __restrict__ O)
{
    const int d  = blockIdx.y * 256 + threadIdx.x;
    const int t0 = blockIdx.x * 16;
    __shared__ float hs[16][64];
    {
        int row = threadIdx.x >> 4;        // 0..15
        int c   = (threadIdx.x & 15) << 2; // 0..60
        *(float4*)&hs[row][c] = *(const float4*)&H[(size_t)(t0 + row) * ERCOL + c];
    }
    __syncthreads();
    float acc[16];
    #pragma unroll
    for (int i = 0; i < 16; i++) acc[i] = 0.f;
    #pragma unroll 4
    for (int c = 0; c < 64; c++) {
        float bv = Bf[(size_t)c * DIM + d];
        #pragma unroll
        for (int i = 0; i < 16; i++) acc[i] = fmaf(hs[i][c], bv, acc[i]);
    }
    #pragma unroll
    for (int i = 0; i < 16; i++) O[(size_t)(t0 + i) * DIM + d] = acc[i];
}

// ---------------------------------------------------------------------------
extern "C" void kernel_launch(void* const* d_in, const int* in_sizes, int n_in,
                              void* d_out, int out_size)
{
    const float* x_ctx  = (const float*)d_in[0];
    const float* x_tgt  = (const float*)d_in[1];
    // per-stack param blocks: Wi, bi, td, Wo, bo, g, beta
    const float* P[2][7];
    for (int i = 0; i < 7; i++) { P[0][i] = (const float*)d_in[2 + i];
                                  P[1][i] = (const float*)d_in[9 + i]; }
    const float* gate_W = (const float*)d_in[16];
    const float* gate_b = (const float*)d_in[17];
    const float* lora_A = (const float*)d_in[18];
    const float* lora_B = (const float*)d_in[19];

    float* out      = (float*)d_out;
    float* out_pred = out;                                  // [TTOK*DIM]
    float* out_gate = out + (size_t)TTOK * DIM;             // [TTOK*4]
    float* out_ztgt = out_gate + (size_t)TTOK * NEXP;       // [TTOK*DIM]

    float *bufA, *bufB, *bufC, *bufH; int* bufM;
    cudaGetSymbolAddress((void**)&bufA, g_bufA);
    cudaGetSymbolAddress((void**)&bufB, g_bufB);
    cudaGetSymbolAddress((void**)&bufC, g_bufC);
    cudaGetSymbolAddress((void**)&bufH, g_H);
    cudaGetSymbolAddress((void**)&bufM, g_maskbuf);

    const dim3 gg(DIM / 128, TTOK / 128);   // (8, 128)

    for (int s = 0; s < 2; s++) {
        const float* Wi   = P[s][0];
        const float* bi   = P[s][1];
        const float* td   = P[s][2];
        const float* Wo   = P[s][3];
        const float* bo   = P[s][4];
        const float* gam  = P[s][5];
        const float* beta = P[s][6];
        const float* xin  = s ? x_tgt : x_ctx;

        for (int l = 0; l < 3; l++) {
            const float* X = (l == 0) ? xin : bufA;
            gemm_dd<0><<<gg, 256>>>(X, Wi + (size_t)l * DIM * DIM,
                                    bi + l * DIM, X, td + l * DIM, bufB);
            gemm_dd<1><<<gg, 256>>>(bufB, Wo + (size_t)l * DIM * DIM,
                                    bo + l * DIM, X, nullptr, bufC);
            float* dst = (s == 1 && l == 2) ? out_ztgt : bufA;
            ln_kernel<<<TTOK, 256>>>(bufC, gam + l * DIM, beta + l * DIM, dst);
        }
        if (s == 0) {
            gate_kernel<<<TTOK, 128>>>(bufA, gate_W, gate_b, out_gate, bufM);
            h_kernel<<<TTOK / 64, 256>>>(bufA, lora_A, bufM, bufH);
            combine_kernel<<<dim3(TTOK / 16, DIM / 256), 256>>>(bufH, lora_B, out_pred);
        }
    }
}

// round 3
// speedup vs baseline: 1.3542x; 1.3542x over previous
#include <cuda_runtime.h>
#include <cuda_bf16.h>
#include <math.h>
#include <stdint.h>

#define TTOK  16384      // B*S
#define DIM   1024
#define NEXP  4
#define RANK  16
#define ERCOL 64
#define LN_EPS 1e-5f

// GEMM tiling
#define BM 128
#define BN 128
#define BK 32
#define KCH   (DIM / BK)     // 32 chunks
#define ROWB  80             // padded row stride in bytes (32 bf16 = 64B + 16B pad)
#define TILEB (128 * ROWB)   // 10240 bytes per matrix tile
#define OFF_AH 0
#define OFF_AL (1 * TILEB)
#define OFF_BH (2 * TILEB)
#define OFF_BL (3 * TILEB)
#define STAGE  (4 * TILEB)   // 40960
#define SMEM_TOTAL (2 * STAGE)  // 81920

// ---------------- scratch (static device memory) ---------------------------
__device__ float g_bufA[(size_t)TTOK * DIM];
__device__ float g_bufB[(size_t)TTOK * DIM];
__device__ float g_bufC[(size_t)TTOK * DIM];
__device__ float g_H[(size_t)TTOK * ERCOL];
__device__ int   g_maskbuf[TTOK];
__device__ __nv_bfloat16 g_Wh[12ull * DIM * DIM];   // transposed bf16-hi weights [N,K]
__device__ __nv_bfloat16 g_Wl[12ull * DIM * DIM];   // transposed bf16-lo weights [N,K]

// ---------------- PTX helpers (base sm_103-safe only) -----------------------
__device__ __forceinline__ uint32_t smem_u32(const void* p) {
    uint32_t a;
    asm("{ .reg .u64 t; cvta.to.shared.u64 t, %1; cvt.u32.u64 %0, t; }" : "=r"(a) : "l"(p));
    return a;
}
#define CP_ASYNC16(dst, src) \
    asm volatile("cp.async.cg.shared.global [%0], [%1], 16;" :: "r"(dst), "l"(src) : "memory")
#define CP_COMMIT() asm volatile("cp.async.commit_group;" ::: "memory")
#define CP_WAIT0()  asm volatile("cp.async.wait_group 0;" ::: "memory")
#define LDSM_X4(r0, r1, r2, r3, addr) \
    asm volatile("ldmatrix.sync.aligned.m8n8.x4.shared.b16 {%0,%1,%2,%3}, [%4];" \
                 : "=r"(r0), "=r"(r1), "=r"(r2), "=r"(r3) : "r"(addr))

__device__ __forceinline__ void mma_bf16(float* d, const uint32_t* a, const uint32_t* b) {
    asm volatile(
        "mma.sync.aligned.m16n8k16.row.col.f32.bf16.bf16.f32 "
        "{%0,%1,%2,%3}, {%4,%5,%6,%7}, {%8,%9}, {%0,%1,%2,%3};"
        : "+f"(d[0]), "+f"(d[1]), "+f"(d[2]), "+f"(d[3])
        : "r"(a[0]), "r"(a[1]), "r"(a[2]), "r"(a[3]), "r"(b[0]), "r"(b[1]));
}

// split 8 fp32 -> 8 bf16 hi + 8 bf16 lo, packed as uint4 each
__device__ __forceinline__ void split8(float4 a, float4 b, uint4& hi, uint4& lo) {
    float f[8] = { a.x, a.y, a.z, a.w, b.x, b.y, b.z, b.w };
    uint32_t h[4], l[4];
    #pragma unroll
    for (int j = 0; j < 4; j++) {
        __nv_bfloat16 h0 = __float2bfloat16(f[2 * j]);
        __nv_bfloat16 h1 = __float2bfloat16(f[2 * j + 1]);
        float r0 = f[2 * j]     - __bfloat162float(h0);
        float r1 = f[2 * j + 1] - __bfloat162float(h1);
        __nv_bfloat16 l0 = __float2bfloat16(r0);
        __nv_bfloat16 l1 = __float2bfloat16(r1);
        h[j] = (uint32_t)__bfloat16_as_ushort(h0) | ((uint32_t)__bfloat16_as_ushort(h1) << 16);
        l[j] = (uint32_t)__bfloat16_as_ushort(l0) | ((uint32_t)__bfloat16_as_ushort(l1) << 16);
    }
    hi = make_uint4(h[0], h[1], h[2], h[3]);
    lo = make_uint4(l[0], l[1], l[2], l[3]);
}

// ---------------------------------------------------------------------------
// Weight transpose + bf16 hi/lo split: W[L,K,N] -> Wh/Wl [L,N,K]
// ---------------------------------------------------------------------------
__global__ __launch_bounds__(256) void wsplit_kernel(
    const float* __restrict__ W, __nv_bfloat16* __restrict__ Wh,
    __nv_bfloat16* __restrict__ Wl)
{
    __shared__ float t[32][33];
    const int l = blockIdx.z;
    const float* Wm = W + (size_t)l * DIM * DIM;
    __nv_bfloat16* Whm = Wh + (size_t)l * DIM * DIM;
    __nv_bfloat16* Wlm = Wl + (size_t)l * DIM * DIM;
    const int n0 = blockIdx.x * 32, k0 = blockIdx.y * 32;
    const int tx = threadIdx.x & 31, ty = threadIdx.x >> 5;   // (32, 8)
    #pragma unroll
    for (int i = 0; i < 4; i++)
        t[ty + i * 8][tx] = Wm[(size_t)(k0 + ty + i * 8) * DIM + n0 + tx];
    __syncthreads();
    #pragma unroll
    for (int i = 0; i < 4; i++) {
        float v = t[tx][ty + i * 8];
        __nv_bfloat16 h = __float2bfloat16(v);
        __nv_bfloat16 lo = __float2bfloat16(v - __bfloat162float(h));
        size_t o = (size_t)(n0 + ty + i * 8) * DIM + k0 + tx;
        Whm[o] = h; Wlm[o] = lo;
    }
}

// ---------------------------------------------------------------------------
// 3xBF16 split GEMM via mma.sync:  C[M,N] = epi(A[M,K] @ W[K,N] + bias)
// W pre-split/transposed to bf16 Wh/Wl [N,K].
//   MODE 0: C = sigmoid(acc + bias) * aux * td
//   MODE 1: C = acc + bias + aux
// CTA 128x128, BK=32, 8 warps (2x4), warp tile 64x32, double-buffered.
// ---------------------------------------------------------------------------
template<int MODE>
__global__ __launch_bounds__(256, 1) void gemm_mma(
    const float* __restrict__ A, const __nv_bfloat16* __restrict__ Wh,
    const __nv_bfloat16* __restrict__ Wl, const float* __restrict__ bias,
    const float* __restrict__ aux, const float* __restrict__ td,
    float* __restrict__ C)
{
    extern __shared__ char smem[];
    const uint32_t sb0 = smem_u32(smem);
    const int tid  = threadIdx.x;
    const int lane = tid & 31;
    const int wid  = tid >> 5;
    const int m0 = blockIdx.y * BM;
    const int n0 = blockIdx.x * BN;
    const int wm0 = (wid >> 2) * 64;   // warp M offset in tile
    const int wn0 = (wid & 3) * 32;    // warp N offset in tile

    float acc[4][4][4];
    #pragma unroll
    for (int mt = 0; mt < 4; mt++)
        #pragma unroll
        for (int nt = 0; nt < 4; nt++)
            #pragma unroll
            for (int j = 0; j < 4; j++) acc[mt][nt][j] = 0.f;

    // -------- initial fill: stage 0, k-chunk 0 --------
    {
        #pragma unroll
        for (int i = 0; i < 2; i++) {
            int cc  = tid + i * 256;
            int row = cc & 127, kb = cc >> 7;
            uint32_t so = (uint32_t)(row * ROWB + kb * 16);
            const size_t gb = (size_t)(n0 + row) * DIM + kb * 8;
            CP_ASYNC16(sb0 + OFF_BH + so, Wh + gb);
            CP_ASYNC16(sb0 + OFF_BL + so, Wl + gb);
            const size_t ga = (size_t)(m0 + row) * DIM + kb * 8;
            float4 v0 = *(const float4*)&A[ga];
            float4 v1 = *(const float4*)&A[ga + 4];
            uint4 hi, lo;
            split8(v0, v1, hi, lo);
            *(uint4*)(smem + OFF_AH + so) = hi;
            *(uint4*)(smem + OFF_AL + so) = lo;
        }
        CP_COMMIT();
        CP_WAIT0();
        __syncthreads();
    }

    const int qr  = lane >> 3;   // ldmatrix matrix id
    const int rr  = lane & 7;

    for (int c = 0; c < KCH; c++) {
        const int st  = c & 1;
        const int nst = st ^ 1;
        const uint32_t sbst = sb0 + st * STAGE;

        // -------- prefetch next chunk: B via cp.async, A into regs --------
        float4 p0[2], p1[2];
        int rowp[2], kbp[2];
        if (c + 1 < KCH) {
            const int k0n = (c + 1) * BK;
            const uint32_t sbn = sb0 + nst * STAGE;
            #pragma unroll
            for (int i = 0; i < 2; i++) {
                int cc  = tid + i * 256;
                rowp[i] = cc & 127; kbp[i] = cc >> 7;
                uint32_t so = (uint32_t)(rowp[i] * ROWB + kbp[i] * 16);
                const size_t gb = (size_t)(n0 + rowp[i]) * DIM + k0n + kbp[i] * 8;
                CP_ASYNC16(sbn + OFF_BH + so, Wh + gb);
                CP_ASYNC16(sbn + OFF_BL + so, Wl + gb);
                const size_t ga = (size_t)(m0 + rowp[i]) * DIM + k0n + kbp[i] * 8;
                p0[i] = *(const float4*)&A[ga];
                p1[i] = *(const float4*)&A[ga + 4];
            }
            CP_COMMIT();
        }

        // -------- compute on stage st --------
        #pragma unroll
        for (int kk = 0; kk < 2; kk++) {
            uint32_t ah[4][4], al[4][4], bh[4][2], bl[4][2];
            // A fragments: matrix q -> rows +(q&1)*8, k8 half = q>>1
            #pragma unroll
            for (int mt = 0; mt < 4; mt++) {
                int arow = wm0 + mt * 16 + rr + (qr & 1) * 8;
                int akb  = kk * 2 + (qr >> 1);
                uint32_t aoff = (uint32_t)(arow * ROWB + akb * 16);
                LDSM_X4(ah[mt][0], ah[mt][1], ah[mt][2], ah[mt][3], sbst + OFF_AH + aoff);
                LDSM_X4(al[mt][0], al[mt][1], al[mt][2], al[mt][3], sbst + OFF_AL + aoff);
            }
            // B fragments: matrix q -> n rows +(q>>1)*8, k8 half = q&1
            #pragma unroll
            for (int ng = 0; ng < 2; ng++) {
                int brow = wn0 + ng * 16 + rr + (qr >> 1) * 8;
                int bkb  = kk * 2 + (qr & 1);
                uint32_t boff = (uint32_t)(brow * ROWB + bkb * 16);
                uint32_t t0, t1, t2, t3;
                LDSM_X4(t0, t1, t2, t3, sbst + OFF_BH + boff);
                bh[ng * 2][0] = t0; bh[ng * 2][1] = t1;
                bh[ng * 2 + 1][0] = t2; bh[ng * 2 + 1][1] = t3;
                LDSM_X4(t0, t1, t2, t3, sbst + OFF_BL + boff);
                bl[ng * 2][0] = t0; bl[ng * 2][1] = t1;
                bl[ng * 2 + 1][0] = t2; bl[ng * 2 + 1][1] = t3;
            }
            // three split passes (hh, hl, lh) - 16 independent accs per pass
            #pragma unroll
            for (int mt = 0; mt < 4; mt++)
                #pragma unroll
                for (int nt = 0; nt < 4; nt++)
                    mma_bf16(acc[mt][nt], ah[mt], bh[nt]);
            #pragma unroll
            for (int mt = 0; mt < 4; mt++)
                #pragma unroll
                for (int nt = 0; nt < 4; nt++)
                    mma_bf16(acc[mt][nt], ah[mt], bl[nt]);
            #pragma unroll
            for (int mt = 0; mt < 4; mt++)
                #pragma unroll
                for (int nt = 0; nt < 4; nt++)
                    mma_bf16(acc[mt][nt], al[mt], bh[nt]);
        }

        // -------- finish prefetch: convert+store A, drain cp.async --------
        if (c + 1 < KCH) {
            #pragma unroll
            for (int i = 0; i < 2; i++) {
                uint32_t so = (uint32_t)(rowp[i] * ROWB + kbp[i] * 16);
                uint4 hi, lo;
                split8(p0[i], p1[i], hi, lo);
                *(uint4*)(smem + nst * STAGE + OFF_AH + so) = hi;
                *(uint4*)(smem + nst * STAGE + OFF_AL + so) = lo;
            }
            CP_WAIT0();
        }
        __syncthreads();
    }

    // -------- epilogue --------
    const int r4 = lane >> 2;          // 0..7
    const int c2 = (lane & 3) * 2;
    #pragma unroll
    for (int mt = 0; mt < 4; mt++) {
        const int row0 = m0 + wm0 + mt * 16 + r4;
        #pragma unroll
        for (int nt = 0; nt < 4; nt++) {
            const int col = n0 + wn0 + nt * 8 + c2;
            float2 bi = *(const float2*)&bias[col];
            float2 tdv;
            if (MODE == 0) tdv = *(const float2*)&td[col];
            #pragma unroll
            for (int half = 0; half < 2; half++) {
                const int rw = row0 + half * 8;
                float2 ax = *(const float2*)&aux[(size_t)rw * DIM + col];
                float v0 = acc[mt][nt][half * 2 + 0] + bi.x;
                float v1 = acc[mt][nt][half * 2 + 1] + bi.y;
                float2 o;
                if (MODE == 0) {
                    float g0 = 1.0f / (1.0f + expf(-v0));
                    float g1 = 1.0f / (1.0f + expf(-v1));
                    o.x = g0 * ax.x * tdv.x;
                    o.y = g1 * ax.y * tdv.y;
                } else {
                    o.x = v0 + ax.x;
                    o.y = v1 + ax.y;
                }
                *(float2*)&C[(size_t)rw * DIM + col] = o;
            }
        }
    }
}

// ---------------------------------------------------------------------------
// Row LayerNorm
// ---------------------------------------------------------------------------
__global__ __launch_bounds__(256) void ln_kernel(
    const float* __restrict__ Y, const float* __restrict__ g,
    const float* __restrict__ beta, float* __restrict__ O)
{
    const int row = blockIdx.x;
    const int tid = threadIdx.x;
    float4 v = *(const float4*)&Y[(size_t)row * DIM + tid * 4];
    float s  = v.x + v.y + v.z + v.w;
    float ss = v.x * v.x + v.y * v.y + v.z * v.z + v.w * v.w;

    __shared__ float rs[8], rss[8];
    #pragma unroll
    for (int o = 16; o > 0; o >>= 1) {
        s  += __shfl_down_sync(0xffffffffu, s,  o);
        ss += __shfl_down_sync(0xffffffffu, ss, o);
    }
    if ((tid & 31) == 0) { rs[tid >> 5] = s; rss[tid >> 5] = ss; }
    __syncthreads();
    float ts = 0.f, tss = 0.f;
    #pragma unroll
    for (int w = 0; w < 8; w++) { ts += rs[w]; tss += rss[w]; }
    float mu   = ts * (1.0f / DIM);
    float var  = tss * (1.0f / DIM) - mu * mu;
    float rstd = rsqrtf(var + LN_EPS);

    float4 g4 = *(const float4*)&g[tid * 4];
    float4 b4 = *(const float4*)&beta[tid * 4];
    float4 o4;
    o4.x = (v.x - mu) * rstd * g4.x + b4.x;
    o4.y = (v.y - mu) * rstd * g4.y + b4.y;
    o4.z = (v.z - mu) * rstd * g4.z + b4.z;
    o4.w = (v.w - mu) * rstd * g4.w + b4.w;
    *(float4*)&O[(size_t)row * DIM + tid * 4] = o4;
}

// ---------------------------------------------------------------------------
// Gate softmax + top-2 mask
// ---------------------------------------------------------------------------
__global__ __launch_bounds__(128) void gate_kernel(
    const float* __restrict__ Z, const float* __restrict__ W,
    const float* __restrict__ b, float* __restrict__ probs_out,
    int* __restrict__ mask_out)
{
    const int t   = blockIdx.x;
    const int tid = threadIdx.x;
    const float* z = Z + (size_t)t * DIM;
    float4 acc = make_float4(0.f, 0.f, 0.f, 0.f);
    for (int d = tid; d < DIM; d += 128) {
        float zv = z[d];
        float4 w = *(const float4*)&W[d * 4];
        acc.x = fmaf(zv, w.x, acc.x);
        acc.y = fmaf(zv, w.y, acc.y);
        acc.z = fmaf(zv, w.z, acc.z);
        acc.w = fmaf(zv, w.w, acc.w);
    }
    __shared__ float4 red[128];
    red[tid] = acc;
    __syncthreads();
    for (int s = 64; s > 0; s >>= 1) {
        if (tid < s) {
            float4 o = red[tid + s];
            red[tid].x += o.x; red[tid].y += o.y;
            red[tid].z += o.z; red[tid].w += o.w;
        }
        __syncthreads();
    }
    if (tid == 0) {
        float l[4] = { red[0].x + b[0], red[0].y + b[1],
                       red[0].z + b[2], red[0].w + b[3] };
        float mx = l[0];
        #pragma unroll
        for (int e = 1; e < 4; e++) mx = fmaxf(mx, l[e]);
        float ex[4], sum = 0.f;
        #pragma unroll
        for (int e = 0; e < 4; e++) { ex[e] = expf(l[e] - mx); sum += ex[e]; }
        float inv = 1.0f / sum;
        #pragma unroll
        for (int e = 0; e < 4; e++) probs_out[(size_t)t * 4 + e] = ex[e] * inv;
        int i1 = 0;
        #pragma unroll
        for (int e = 1; e < 4; e++) if (l[e] > l[i1]) i1 = e;
        int i2 = -1;
        #pragma unroll
        for (int e = 0; e < 4; e++) {
            if (e == i1) continue;
            if (i2 < 0 || l[e] > l[i2]) i2 = e;
        }
        mask_out[t] = (1 << i1) | (1 << i2);
    }
}

// ---------------------------------------------------------------------------
// H = mask * gelu(Z @ Aflat)
// ---------------------------------------------------------------------------
__global__ __launch_bounds__(256) void h_kernel(
    const float* __restrict__ Z, const float* __restrict__ loraA,
    const int* __restrict__ mask, float* __restrict__ H)
{
    __shared__ float Zs[16][68];
    __shared__ float Afs[16][64];

    const int m0  = blockIdx.x * 64;
    const int tid = threadIdx.x;
    const int ty  = tid >> 4;
    const int tx  = tid & 15;

    float acc[4][4];
    #pragma unroll
    for (int i = 0; i < 4; i++)
        #pragma unroll
        for (int j = 0; j < 4; j++) acc[i][j] = 0.f;

    for (int k0 = 0; k0 < DIM; k0 += 16) {
        {
            int row = tid >> 2;
            int kq  = (tid & 3) << 2;
            float4 v = *(const float4*)&Z[(size_t)(m0 + row) * DIM + k0 + kq];
            Zs[kq + 0][row] = v.x; Zs[kq + 1][row] = v.y;
            Zs[kq + 2][row] = v.z; Zs[kq + 3][row] = v.w;
        }
        {
            int k  = tid >> 4;
            int c4 = (tid & 15) << 2;
            int e  = c4 >> 4;
            int r  = c4 & 15;
            float4 v = *(const float4*)&loraA[(size_t)e * DIM * RANK + (size_t)(k0 + k) * RANK + r];
            *(float4*)&Afs[k][c4] = v;
        }
        __syncthreads();
        #pragma unroll
        for (int k = 0; k < 16; k++) {
            float a[4], b[4];
            *(float4*)&a[0] = *(float4*)&Zs[k][ty * 4];
            *(float4*)&b[0] = *(float4*)&Afs[k][tx * 4];
            #pragma unroll
            for (int i = 0; i < 4; i++)
                #pragma unroll
                for (int j = 0; j < 4; j++)
                    acc[i][j] = fmaf(a[i], b[j], acc[i][j]);
        }
        __syncthreads();
    }

    #pragma unroll
    for (int i = 0; i < 4; i++) {
        int m  = m0 + ty * 4 + i;
        int mk = mask[m];
        #pragma unroll
        for (int j = 0; j < 4; j++) {
            int c = tx * 4 + j;
            int e = c >> 4;
            float x = acc[i][j];
            float h = 0.5f * x * (1.0f + erff(x * 0.70710678118654752f));
            H[(size_t)m * ERCOL + c] = ((mk >> e) & 1) ? h : 0.0f;
        }
    }
}

// ---------------------------------------------------------------------------
// pred = H @ Bflat
// ---------------------------------------------------------------------------
__global__ __launch_bounds__(256) void combine_kernel(
    const float* __restrict__ H, const float* __restrict__ Bf,
    float* __restrict__ O)
{
    const int d  = blockIdx.y * 256 + threadIdx.x;
    const int t0 = blockIdx.x * 16;
    __shared__ float hs[16][64];
    {
        int row = threadIdx.x >> 4;
        int c   = (threadIdx.x & 15) << 2;
        *(float4*)&hs[row][c] = *(const float4*)&H[(size_t)(t0 + row) * ERCOL + c];
    }
    __syncthreads();
    float acc[16];
    #pragma unroll
    for (int i = 0; i < 16; i++) acc[i] = 0.f;
    #pragma unroll 4
    for (int c = 0; c < 64; c++) {
        float bv = Bf[(size_t)c * DIM + d];
        #pragma unroll
        for (int i = 0; i < 16; i++) acc[i] = fmaf(hs[i][c], bv, acc[i]);
    }
    #pragma unroll
    for (int i = 0; i < 16; i++) O[(size_t)(t0 + i) * DIM + d] = acc[i];
}

// ---------------------------------------------------------------------------
extern "C" void kernel_launch(void* const* d_in, const int* in_sizes, int n_in,
                              void* d_out, int out_size)
{
    const float* x_ctx  = (const float*)d_in[0];
    const float* x_tgt  = (const float*)d_in[1];
    const float* P[2][7];
    for (int i = 0; i < 7; i++) { P[0][i] = (const float*)d_in[2 + i];
                                  P[1][i] = (const float*)d_in[9 + i]; }
    const float* gate_W = (const float*)d_in[16];
    const float* gate_b = (const float*)d_in[17];
    const float* lora_A = (const float*)d_in[18];
    const float* lora_B = (const float*)d_in[19];

    float* out      = (float*)d_out;
    float* out_pred = out;
    float* out_gate = out + (size_t)TTOK * DIM;
    float* out_ztgt = out_gate + (size_t)TTOK * NEXP;

    float *bufA, *bufB, *bufC, *bufH; int* bufM;
    __nv_bfloat16 *Wh, *Wl;
    cudaGetSymbolAddress((void**)&bufA, g_bufA);
    cudaGetSymbolAddress((void**)&bufB, g_bufB);
    cudaGetSymbolAddress((void**)&bufC, g_bufC);
    cudaGetSymbolAddress((void**)&bufH, g_H);
    cudaGetSymbolAddress((void**)&Wh,   g_Wh);
    cudaGetSymbolAddress((void**)&Wl,   g_Wl);
    cudaGetSymbolAddress((void**)&bufM, g_maskbuf);

    cudaFuncSetAttribute(gemm_mma<0>, cudaFuncAttributeMaxDynamicSharedMemorySize, SMEM_TOTAL);
    cudaFuncSetAttribute(gemm_mma<1>, cudaFuncAttributeMaxDynamicSharedMemorySize, SMEM_TOTAL);

    const size_t MM = (size_t)DIM * DIM;
    // converted weight slots: [s*6 + l] = Wi(s,l), [s*6 + 3 + l] = Wo(s,l)
    const dim3 wg(32, 32, 3), wb(256);
    wsplit_kernel<<<wg, wb>>>(P[0][0], Wh + 0 * MM, Wl + 0 * MM);
    wsplit_kernel<<<wg, wb>>>(P[0][3], Wh + 3 * MM, Wl + 3 * MM);
    wsplit_kernel<<<wg, wb>>>(P[1][0], Wh + 6 * MM, Wl + 6 * MM);
    wsplit_kernel<<<wg, wb>>>(P[1][3], Wh + 9 * MM, Wl + 9 * MM);

    const dim3 gg(DIM / BN, TTOK / BM);   // (8, 128)

    for (int s = 0; s < 2; s++) {
        const float* bi   = P[s][1];
        const float* td   = P[s][2];
        const float* bo   = P[s][4];
        const float* gam  = P[s][5];
        const float* beta = P[s][6];
        const float* xin  = s ? x_tgt : x_ctx;

        for (int l = 0; l < 3; l++) {
            const float* X = (l == 0) ? xin : bufA;
            const size_t wiOff = (size_t)(s * 6 + l) * MM;
            const size_t woOff = (size_t)(s * 6 + 3 + l) * MM;
            gemm_mma<0><<<gg, 256, SMEM_TOTAL>>>(X, Wh + wiOff, Wl + wiOff,
                                                 bi + l * DIM, X, td + l * DIM, bufB);
            gemm_mma<1><<<gg, 256, SMEM_TOTAL>>>(bufB, Wh + woOff, Wl + woOff,
                                                 bo + l * DIM, X, nullptr, bufC);
            float* dst = (s == 1 && l == 2) ? out_ztgt : bufA;
            ln_kernel<<<TTOK, 256>>>(bufC, gam + l * DIM, beta + l * DIM, dst);
        }
        if (s == 0) {
            gate_kernel<<<TTOK, 128>>>(bufA, gate_W, gate_b, out_gate, bufM);
            h_kernel<<<TTOK / 64, 256>>>(bufA, lora_A, bufM, bufH);
            combine_kernel<<<dim3(TTOK / 16, DIM / 256), 256>>>(bufH, lora_B, out_pred);
        }
    }
}

// round 4
// speedup vs baseline: 1.5530x; 1.1468x over previous
#include <cuda_runtime.h>
#include <cuda_bf16.h>
#include <math.h>
#include <stdint.h>

#define TTOK  16384      // B*S
#define DIM   1024
#define NEXP  4
#define RANK  16
#define ERCOL 64
#define LN_EPS 1e-5f

// GEMM tiling
#define BM 128
#define BN 128
#define BK 32
#define KCH   (DIM / BK)     // 32 chunks
#define ROWB  80             // padded row stride bytes (64B data + 16B pad, 16B-mult)
#define TILEB (128 * ROWB)   // 10240 bytes per matrix tile
#define OFF_AH 0
#define OFF_AL (1 * TILEB)
#define OFF_BH (2 * TILEB)
#define OFF_BL (3 * TILEB)
#define STAGE  (4 * TILEB)   // 40960
#define NSTAGE 4
#define SMEM_TOTAL (NSTAGE * STAGE)  // 163840

// ---------------- scratch (static device memory) ---------------------------
__device__ float g_bufA[(size_t)TTOK * DIM];                 // fp32 activations (aux/LN out)
__device__ float g_bufC[(size_t)TTOK * DIM];                 // pre-LN y
__device__ float g_H[(size_t)TTOK * ERCOL];
__device__ int   g_maskbuf[TTOK];
__device__ __nv_bfloat16 g_Ah[(size_t)TTOK * DIM];           // activation hi
__device__ __nv_bfloat16 g_Al[(size_t)TTOK * DIM];           // activation lo
__device__ __nv_bfloat16 g_Bh[(size_t)TTOK * DIM];           // new_state hi
__device__ __nv_bfloat16 g_Bl[(size_t)TTOK * DIM];           // new_state lo
__device__ __nv_bfloat16 g_Wh[12ull * DIM * DIM];            // transposed weight hi [N,K]
__device__ __nv_bfloat16 g_Wl[12ull * DIM * DIM];            // transposed weight lo [N,K]

// ---------------- PTX helpers (base sm_103-safe only) -----------------------
__device__ __forceinline__ uint32_t smem_u32(const void* p) {
    uint32_t a;
    asm("{ .reg .u64 t; cvta.to.shared.u64 t, %1; cvt.u32.u64 %0, t; }" : "=r"(a) : "l"(p));
    return a;
}
#define CP_ASYNC16(dst, src) \
    asm volatile("cp.async.cg.shared.global [%0], [%1], 16;" :: "r"(dst), "l"(src) : "memory")
#define CP_COMMIT() asm volatile("cp.async.commit_group;" ::: "memory")
#define CP_WAIT2()  asm volatile("cp.async.wait_group 2;" ::: "memory")
#define LDSM_X4(r0, r1, r2, r3, addr) \
    asm volatile("ldmatrix.sync.aligned.m8n8.x4.shared.b16 {%0,%1,%2,%3}, [%4];" \
                 : "=r"(r0), "=r"(r1), "=r"(r2), "=r"(r3) : "r"(addr))

__device__ __forceinline__ void mma_bf16(float* d, const uint32_t* a, const uint32_t* b) {
    asm volatile(
        "mma.sync.aligned.m16n8k16.row.col.f32.bf16.bf16.f32 "
        "{%0,%1,%2,%3}, {%4,%5,%6,%7}, {%8,%9}, {%0,%1,%2,%3};"
        : "+f"(d[0]), "+f"(d[1]), "+f"(d[2]), "+f"(d[3])
        : "r"(a[0]), "r"(a[1]), "r"(a[2]), "r"(a[3]), "r"(b[0]), "r"(b[1]));
}

__device__ __forceinline__ uint32_t pack_bf16x2(float a, float b) {
    __nv_bfloat16 h0 = __float2bfloat16(a);
    __nv_bfloat16 h1 = __float2bfloat16(b);
    return (uint32_t)__bfloat16_as_ushort(h0) | ((uint32_t)__bfloat16_as_ushort(h1) << 16);
}

// ---------------------------------------------------------------------------
// Input split: X fp32 -> bf16 hi/lo
// ---------------------------------------------------------------------------
__global__ __launch_bounds__(256) void split_x(
    const float* __restrict__ X, __nv_bfloat16* __restrict__ H,
    __nv_bfloat16* __restrict__ L)
{
    const size_t i = ((size_t)blockIdx.x * 256 + threadIdx.x) * 4;
    float4 v = *(const float4*)&X[i];
    float hx = __bfloat162float(__float2bfloat16(v.x));
    float hy = __bfloat162float(__float2bfloat16(v.y));
    float hz = __bfloat162float(__float2bfloat16(v.z));
    float hw = __bfloat162float(__float2bfloat16(v.w));
    uint2 hp = make_uint2(pack_bf16x2(v.x, v.y), pack_bf16x2(v.z, v.w));
    uint2 lp = make_uint2(pack_bf16x2(v.x - hx, v.y - hy), pack_bf16x2(v.z - hz, v.w - hw));
    *(uint2*)&H[i] = hp;
    *(uint2*)&L[i] = lp;
}

// ---------------------------------------------------------------------------
// Weight transpose + bf16 hi/lo split: W[L,K,N] -> Wh/Wl [L,N,K]
// ---------------------------------------------------------------------------
__global__ __launch_bounds__(256) void wsplit_kernel(
    const float* __restrict__ W, __nv_bfloat16* __restrict__ Wh,
    __nv_bfloat16* __restrict__ Wl)
{
    __shared__ float t[32][33];
    const int l = blockIdx.z;
    const float* Wm = W + (size_t)l * DIM * DIM;
    __nv_bfloat16* Whm = Wh + (size_t)l * DIM * DIM;
    __nv_bfloat16* Wlm = Wl + (size_t)l * DIM * DIM;
    const int n0 = blockIdx.x * 32, k0 = blockIdx.y * 32;
    const int tx = threadIdx.x & 31, ty = threadIdx.x >> 5;
    #pragma unroll
    for (int i = 0; i < 4; i++)
        t[ty + i * 8][tx] = Wm[(size_t)(k0 + ty + i * 8) * DIM + n0 + tx];
    __syncthreads();
    #pragma unroll
    for (int i = 0; i < 4; i++) {
        float v = t[tx][ty + i * 8];
        __nv_bfloat16 h = __float2bfloat16(v);
        __nv_bfloat16 lo = __float2bfloat16(v - __bfloat162float(h));
        size_t o = (size_t)(n0 + ty + i * 8) * DIM + k0 + tx;
        Whm[o] = h; Wlm[o] = lo;
    }
}

// ---------------------------------------------------------------------------
// 3xBF16 split GEMM via mma.sync, fully cp.async, 4-stage pipeline.
// A given pre-split bf16 (Ah/Al [M,K]); W pre-split/transposed (Wh/Wl [N,K]).
//   MODE 0: o = sigmoid(acc + bias) * aux * td  -> written as bf16 hi/lo (Ch/Cl)
//   MODE 1: o = acc + bias + aux                -> written fp32 (C)
// CTA 128x128, BK=32, 8 warps (2x4), warp tile 64x32.
// ---------------------------------------------------------------------------
template<int MODE>
__global__ __launch_bounds__(256, 1) void gemm_mma(
    const __nv_bfloat16* __restrict__ Ah, const __nv_bfloat16* __restrict__ Al,
    const __nv_bfloat16* __restrict__ Wh, const __nv_bfloat16* __restrict__ Wl,
    const float* __restrict__ bias, const float* __restrict__ aux,
    const float* __restrict__ td, float* __restrict__ C,
    __nv_bfloat16* __restrict__ Ch, __nv_bfloat16* __restrict__ Cl)
{
    extern __shared__ char smem[];
    const uint32_t sb0 = smem_u32(smem);
    const int tid  = threadIdx.x;
    const int lane = tid & 31;
    const int wid  = tid >> 5;
    const int m0 = blockIdx.y * BM;
    const int n0 = blockIdx.x * BN;
    const int wm0 = (wid >> 2) * 64;
    const int wn0 = (wid & 3) * 32;

    float acc[4][4][4];
    #pragma unroll
    for (int mt = 0; mt < 4; mt++)
        #pragma unroll
        for (int nt = 0; nt < 4; nt++)
            #pragma unroll
            for (int j = 0; j < 4; j++) acc[mt][nt][j] = 0.f;

    // per-thread transfer slots: 512 (row,kb) pairs over 2 iterations
    const int cc0 = tid, cc1 = tid + 256;
    const int row0 = cc0 & 127, kb0 = cc0 >> 7;
    const int row1 = cc1 & 127, kb1 = cc1 >> 7;

    auto load_chunk = [&](int c, int st) {
        const int k0c = c * BK;
        const uint32_t sbn = sb0 + st * STAGE;
        {
            uint32_t so = (uint32_t)(row0 * ROWB + kb0 * 16);
            const size_t ga = (size_t)(m0 + row0) * DIM + k0c + kb0 * 8;
            const size_t gb = (size_t)(n0 + row0) * DIM + k0c + kb0 * 8;
            CP_ASYNC16(sbn + OFF_AH + so, Ah + ga);
            CP_ASYNC16(sbn + OFF_AL + so, Al + ga);
            CP_ASYNC16(sbn + OFF_BH + so, Wh + gb);
            CP_ASYNC16(sbn + OFF_BL + so, Wl + gb);
        }
        {
            uint32_t so = (uint32_t)(row1 * ROWB + kb1 * 16);
            const size_t ga = (size_t)(m0 + row1) * DIM + k0c + kb1 * 8;
            const size_t gb = (size_t)(n0 + row1) * DIM + k0c + kb1 * 8;
            CP_ASYNC16(sbn + OFF_AH + so, Ah + ga);
            CP_ASYNC16(sbn + OFF_AL + so, Al + ga);
            CP_ASYNC16(sbn + OFF_BH + so, Wh + gb);
            CP_ASYNC16(sbn + OFF_BL + so, Wl + gb);
        }
        CP_COMMIT();
    };

    // prologue: prefetch 3 chunks
    load_chunk(0, 0);
    load_chunk(1, 1);
    load_chunk(2, 2);
    CP_WAIT2();          // chunk 0 complete
    __syncthreads();

    const int qr = lane >> 3;
    const int rr = lane & 7;

    for (int c = 0; c < KCH; c++) {
        const uint32_t sbst = sb0 + (c & 3) * STAGE;

        #pragma unroll
        for (int kk = 0; kk < 2; kk++) {
            uint32_t ah[4][4], al[4][4], bh[4][2], bl[4][2];
            #pragma unroll
            for (int mt = 0; mt < 4; mt++) {
                int arow = wm0 + mt * 16 + rr + (qr & 1) * 8;
                int akb  = kk * 2 + (qr >> 1);
                uint32_t aoff = (uint32_t)(arow * ROWB + akb * 16);
                LDSM_X4(ah[mt][0], ah[mt][1], ah[mt][2], ah[mt][3], sbst + OFF_AH + aoff);
                LDSM_X4(al[mt][0], al[mt][1], al[mt][2], al[mt][3], sbst + OFF_AL + aoff);
            }
            #pragma unroll
            for (int ng = 0; ng < 2; ng++) {
                int brow = wn0 + ng * 16 + rr + (qr >> 1) * 8;
                int bkb  = kk * 2 + (qr & 1);
                uint32_t boff = (uint32_t)(brow * ROWB + bkb * 16);
                uint32_t t0, t1, t2, t3;
                LDSM_X4(t0, t1, t2, t3, sbst + OFF_BH + boff);
                bh[ng * 2][0] = t0; bh[ng * 2][1] = t1;
                bh[ng * 2 + 1][0] = t2; bh[ng * 2 + 1][1] = t3;
                LDSM_X4(t0, t1, t2, t3, sbst + OFF_BL + boff);
                bl[ng * 2][0] = t0; bl[ng * 2][1] = t1;
                bl[ng * 2 + 1][0] = t2; bl[ng * 2 + 1][1] = t3;
            }
            #pragma unroll
            for (int mt = 0; mt < 4; mt++)
                #pragma unroll
                for (int nt = 0; nt < 4; nt++)
                    mma_bf16(acc[mt][nt], ah[mt], bh[nt]);
            #pragma unroll
            for (int mt = 0; mt < 4; mt++)
                #pragma unroll
                for (int nt = 0; nt < 4; nt++)
                    mma_bf16(acc[mt][nt], ah[mt], bl[nt]);
            #pragma unroll
            for (int mt = 0; mt < 4; mt++)
                #pragma unroll
                for (int nt = 0; nt < 4; nt++)
                    mma_bf16(acc[mt][nt], al[mt], bh[nt]);
        }

        if (c + 3 < KCH) load_chunk(c + 3, (c + 3) & 3);
        else             CP_COMMIT();   // empty group keeps wait bookkeeping uniform
        CP_WAIT2();                     // next chunk's data now resident
        __syncthreads();
    }

    // -------- epilogue --------
    const int r4 = lane >> 2;
    const int c2 = (lane & 3) * 2;
    #pragma unroll
    for (int mt = 0; mt < 4; mt++) {
        const int rowb = m0 + wm0 + mt * 16 + r4;
        #pragma unroll
        for (int nt = 0; nt < 4; nt++) {
            const int col = n0 + wn0 + nt * 8 + c2;
            float2 bi = *(const float2*)&bias[col];
            float2 tdv;
            if (MODE == 0) tdv = *(const float2*)&td[col];
            #pragma unroll
            for (int half = 0; half < 2; half++) {
                const int rw = rowb + half * 8;
                float2 ax = *(const float2*)&aux[(size_t)rw * DIM + col];
                float v0 = acc[mt][nt][half * 2 + 0] + bi.x;
                float v1 = acc[mt][nt][half * 2 + 1] + bi.y;
                if (MODE == 0) {
                    float g0 = 1.0f / (1.0f + expf(-v0));
                    float g1 = 1.0f / (1.0f + expf(-v1));
                    float o0 = g0 * ax.x * tdv.x;
                    float o1 = g1 * ax.y * tdv.y;
                    float h0 = __bfloat162float(__float2bfloat16(o0));
                    float h1 = __bfloat162float(__float2bfloat16(o1));
                    *(uint32_t*)&Ch[(size_t)rw * DIM + col] = pack_bf16x2(o0, o1);
                    *(uint32_t*)&Cl[(size_t)rw * DIM + col] = pack_bf16x2(o0 - h0, o1 - h1);
                } else {
                    float2 o = make_float2(v0 + ax.x, v1 + ax.y);
                    *(float2*)&C[(size_t)rw * DIM + col] = o;
                }
            }
        }
    }
}

// ---------------------------------------------------------------------------
// Row LayerNorm: fp32 out + bf16 hi/lo out
// ---------------------------------------------------------------------------
__global__ __launch_bounds__(256) void ln_kernel(
    const float* __restrict__ Y, const float* __restrict__ g,
    const float* __restrict__ beta, float* __restrict__ O,
    __nv_bfloat16* __restrict__ Oh, __nv_bfloat16* __restrict__ Ol)
{
    const int row = blockIdx.x;
    const int tid = threadIdx.x;
    float4 v = *(const float4*)&Y[(size_t)row * DIM + tid * 4];
    float s  = v.x + v.y + v.z + v.w;
    float ss = v.x * v.x + v.y * v.y + v.z * v.z + v.w * v.w;

    __shared__ float rs[8], rss[8];
    #pragma unroll
    for (int o = 16; o > 0; o >>= 1) {
        s  += __shfl_down_sync(0xffffffffu, s,  o);
        ss += __shfl_down_sync(0xffffffffu, ss, o);
    }
    if ((tid & 31) == 0) { rs[tid >> 5] = s; rss[tid >> 5] = ss; }
    __syncthreads();
    float ts = 0.f, tss = 0.f;
    #pragma unroll
    for (int w = 0; w < 8; w++) { ts += rs[w]; tss += rss[w]; }
    float mu   = ts * (1.0f / DIM);
    float var  = tss * (1.0f / DIM) - mu * mu;
    float rstd = rsqrtf(var + LN_EPS);

    float4 g4 = *(const float4*)&g[tid * 4];
    float4 b4 = *(const float4*)&beta[tid * 4];
    float4 o4;
    o4.x = (v.x - mu) * rstd * g4.x + b4.x;
    o4.y = (v.y - mu) * rstd * g4.y + b4.y;
    o4.z = (v.z - mu) * rstd * g4.z + b4.z;
    o4.w = (v.w - mu) * rstd * g4.w + b4.w;
    const size_t base = (size_t)row * DIM + tid * 4;
    *(float4*)&O[base] = o4;
    float hx = __bfloat162float(__float2bfloat16(o4.x));
    float hy = __bfloat162float(__float2bfloat16(o4.y));
    float hz = __bfloat162float(__float2bfloat16(o4.z));
    float hw = __bfloat162float(__float2bfloat16(o4.w));
    *(uint2*)&Oh[base] = make_uint2(pack_bf16x2(o4.x, o4.y), pack_bf16x2(o4.z, o4.w));
    *(uint2*)&Ol[base] = make_uint2(pack_bf16x2(o4.x - hx, o4.y - hy),
                                    pack_bf16x2(o4.z - hz, o4.w - hw));
}

// ---------------------------------------------------------------------------
// Gate softmax + top-2 mask
// ---------------------------------------------------------------------------
__global__ __launch_bounds__(128) void gate_kernel(
    const float* __restrict__ Z, const float* __restrict__ W,
    const float* __restrict__ b, float* __restrict__ probs_out,
    int* __restrict__ mask_out)
{
    const int t   = blockIdx.x;
    const int tid = threadIdx.x;
    const float* z = Z + (size_t)t * DIM;
    float4 acc = make_float4(0.f, 0.f, 0.f, 0.f);
    for (int d = tid; d < DIM; d += 128) {
        float zv = z[d];
        float4 w = *(const float4*)&W[d * 4];
        acc.x = fmaf(zv, w.x, acc.x);
        acc.y = fmaf(zv, w.y, acc.y);
        acc.z = fmaf(zv, w.z, acc.z);
        acc.w = fmaf(zv, w.w, acc.w);
    }
    __shared__ float4 red[128];
    red[tid] = acc;
    __syncthreads();
    for (int s = 64; s > 0; s >>= 1) {
        if (tid < s) {
            float4 o = red[tid + s];
            red[tid].x += o.x; red[tid].y += o.y;
            red[tid].z += o.z; red[tid].w += o.w;
        }
        __syncthreads();
    }
    if (tid == 0) {
        float l[4] = { red[0].x + b[0], red[0].y + b[1],
                       red[0].z + b[2], red[0].w + b[3] };
        float mx = l[0];
        #pragma unroll
        for (int e = 1; e < 4; e++) mx = fmaxf(mx, l[e]);
        float ex[4], sum = 0.f;
        #pragma unroll
        for (int e = 0; e < 4; e++) { ex[e] = expf(l[e] - mx); sum += ex[e]; }
        float inv = 1.0f / sum;
        #pragma unroll
        for (int e = 0; e < 4; e++) probs_out[(size_t)t * 4 + e] = ex[e] * inv;
        int i1 = 0;
        #pragma unroll
        for (int e = 1; e < 4; e++) if (l[e] > l[i1]) i1 = e;
        int i2 = -1;
        #pragma unroll
        for (int e = 0; e < 4; e++) {
            if (e == i1) continue;
            if (i2 < 0 || l[e] > l[i2]) i2 = e;
        }
        mask_out[t] = (1 << i1) | (1 << i2);
    }
}

// ---------------------------------------------------------------------------
// H = mask * gelu(Z @ Aflat)
// ---------------------------------------------------------------------------
__global__ __launch_bounds__(256) void h_kernel(
    const float* __restrict__ Z, const float* __restrict__ loraA,
    const int* __restrict__ mask, float* __restrict__ H)
{
    __shared__ float Zs[16][68];
    __shared__ float Afs[16][64];

    const int m0  = blockIdx.x * 64;
    const int tid = threadIdx.x;
    const int ty  = tid >> 4;
    const int tx  = tid & 15;

    float acc[4][4];
    #pragma unroll
    for (int i = 0; i < 4; i++)
        #pragma unroll
        for (int j = 0; j < 4; j++) acc[i][j] = 0.f;

    for (int k0 = 0; k0 < DIM; k0 += 16) {
        {
            int row = tid >> 2;
            int kq  = (tid & 3) << 2;
            float4 v = *(const float4*)&Z[(size_t)(m0 + row) * DIM + k0 + kq];
            Zs[kq + 0][row] = v.x; Zs[kq + 1][row] = v.y;
            Zs[kq + 2][row] = v.z; Zs[kq + 3][row] = v.w;
        }
        {
            int k  = tid >> 4;
            int c4 = (tid & 15) << 2;
            int e  = c4 >> 4;
            int r  = c4 & 15;
            float4 v = *(const float4*)&loraA[(size_t)e * DIM * RANK + (size_t)(k0 + k) * RANK + r];
            *(float4*)&Afs[k][c4] = v;
        }
        __syncthreads();
        #pragma unroll
        for (int k = 0; k < 16; k++) {
            float a[4], b[4];
            *(float4*)&a[0] = *(float4*)&Zs[k][ty * 4];
            *(float4*)&b[0] = *(float4*)&Afs[k][tx * 4];
            #pragma unroll
            for (int i = 0; i < 4; i++)
                #pragma unroll
                for (int j = 0; j < 4; j++)
                    acc[i][j] = fmaf(a[i], b[j], acc[i][j]);
        }
        __syncthreads();
    }

    #pragma unroll
    for (int i = 0; i < 4; i++) {
        int m  = m0 + ty * 4 + i;
        int mk = mask[m];
        #pragma unroll
        for (int j = 0; j < 4; j++) {
            int c = tx * 4 + j;
            int e = c >> 4;
            float x = acc[i][j];
            float h = 0.5f * x * (1.0f + erff(x * 0.70710678118654752f));
            H[(size_t)m * ERCOL + c] = ((mk >> e) & 1) ? h : 0.0f;
        }
    }
}

// ---------------------------------------------------------------------------
// pred = H @ Bflat
// ---------------------------------------------------------------------------
__global__ __launch_bounds__(256) void combine_kernel(
    const float* __restrict__ H, const float* __restrict__ Bf,
    float* __restrict__ O)
{
    const int d  = blockIdx.y * 256 + threadIdx.x;
    const int t0 = blockIdx.x * 16;
    __shared__ float hs[16][64];
    {
        int row = threadIdx.x >> 4;
        int c   = (threadIdx.x & 15) << 2;
        *(float4*)&hs[row][c] = *(const float4*)&H[(size_t)(t0 + row) * ERCOL + c];
    }
    __syncthreads();
    float acc[16];
    #pragma unroll
    for (int i = 0; i < 16; i++) acc[i] = 0.f;
    #pragma unroll 4
    for (int c = 0; c < 64; c++) {
        float bv = Bf[(size_t)c * DIM + d];
        #pragma unroll
        for (int i = 0; i < 16; i++) acc[i] = fmaf(hs[i][c], bv, acc[i]);
    }
    #pragma unroll
    for (int i = 0; i < 16; i++) O[(size_t)(t0 + i) * DIM + d] = acc[i];
}

// ---------------------------------------------------------------------------
extern "C" void kernel_launch(void* const* d_in, const int* in_sizes, int n_in,
                              void* d_out, int out_size)
{
    const float* x_ctx  = (const float*)d_in[0];
    const float* x_tgt  = (const float*)d_in[1];
    const float* P[2][7];
    for (int i = 0; i < 7; i++) { P[0][i] = (const float*)d_in[2 + i];
                                  P[1][i] = (const float*)d_in[9 + i]; }
    const float* gate_W = (const float*)d_in[16];
    const float* gate_b = (const float*)d_in[17];
    const float* lora_A = (const float*)d_in[18];
    const float* lora_B = (const float*)d_in[19];

    float* out      = (float*)d_out;
    float* out_pred = out;
    float* out_gate = out + (size_t)TTOK * DIM;
    float* out_ztgt = out_gate + (size_t)TTOK * NEXP;

    float *bufA, *bufC, *bufH; int* bufM;
    __nv_bfloat16 *Ah, *Al, *Bh, *Bl, *Wh, *Wl;
    cudaGetSymbolAddress((void**)&bufA, g_bufA);
    cudaGetSymbolAddress((void**)&bufC, g_bufC);
    cudaGetSymbolAddress((void**)&bufH, g_H);
    cudaGetSymbolAddress((void**)&Ah,   g_Ah);
    cudaGetSymbolAddress((void**)&Al,   g_Al);
    cudaGetSymbolAddress((void**)&Bh,   g_Bh);
    cudaGetSymbolAddress((void**)&Bl,   g_Bl);
    cudaGetSymbolAddress((void**)&Wh,   g_Wh);
    cudaGetSymbolAddress((void**)&Wl,   g_Wl);
    cudaGetSymbolAddress((void**)&bufM, g_maskbuf);

    cudaFuncSetAttribute(gemm_mma<0>, cudaFuncAttributeMaxDynamicSharedMemorySize, SMEM_TOTAL);
    cudaFuncSetAttribute(gemm_mma<1>, cudaFuncAttributeMaxDynamicSharedMemorySize, SMEM_TOTAL);

    const size_t MM = (size_t)DIM * DIM;
    const dim3 wg(32, 32, 3), wb(256);
    wsplit_kernel<<<wg, wb>>>(P[0][0], Wh + 0 * MM, Wl + 0 * MM);
    wsplit_kernel<<<wg, wb>>>(P[0][3], Wh + 3 * MM, Wl + 3 * MM);
    wsplit_kernel<<<wg, wb>>>(P[1][0], Wh + 6 * MM, Wl + 6 * MM);
    wsplit_kernel<<<wg, wb>>>(P[1][3], Wh + 9 * MM, Wl + 9 * MM);

    const dim3 gg(DIM / BN, TTOK / BM);   // (8, 128)
    const int splitGrid = (TTOK * DIM) / 1024;

    for (int s = 0; s < 2; s++) {
        const float* bi   = P[s][1];
        const float* td   = P[s][2];
        const float* bo   = P[s][4];
        const float* gam  = P[s][5];
        const float* beta = P[s][6];
        const float* xin  = s ? x_tgt : x_ctx;

        split_x<<<splitGrid, 256>>>(xin, Ah, Al);

        for (int l = 0; l < 3; l++) {
            const float* X = (l == 0) ? xin : bufA;   // fp32 aux/residual source
            const size_t wiOff = (size_t)(s * 6 + l) * MM;
            const size_t woOff = (size_t)(s * 6 + 3 + l) * MM;
            gemm_mma<0><<<gg, 256, SMEM_TOTAL>>>(Ah, Al, Wh + wiOff, Wl + wiOff,
                                                 bi + l * DIM, X, td + l * DIM,
                                                 nullptr, Bh, Bl);
            gemm_mma<1><<<gg, 256, SMEM_TOTAL>>>(Bh, Bl, Wh + woOff, Wl + woOff,
                                                 bo + l * DIM, X, nullptr,
                                                 bufC, nullptr, nullptr);
            float* dst = (s == 1 && l == 2) ? out_ztgt : bufA;
            ln_kernel<<<TTOK, 256>>>(bufC, gam + l * DIM, beta + l * DIM, dst, Ah, Al);
        }
        if (s == 0) {
            gate_kernel<<<TTOK, 128>>>(bufA, gate_W, gate_b, out_gate, bufM);
            h_kernel<<<TTOK / 64, 256>>>(bufA, lora_A, bufM, bufH);
            combine_kernel<<<dim3(TTOK / 16, DIM / 256), 256>>>(bufH, lora_B, out_pred);
        }
    }
}

// round 5
// speedup vs baseline: 1.6945x; 1.0911x over previous
#include <cuda_runtime.h>
#include <cuda_bf16.h>
#include <math.h>
#include <stdint.h>

#define TTOK  16384      // B*S
#define DIM   1024
#define NEXP  4
#define RANK  16
#define ERCOL 64
#define LN_EPS 1e-5f

// GEMM tiling
#define BM 128
#define BN 128
#define BK 32
#define KCH   (DIM / BK)     // 32 chunks
#define ROWB  80             // padded row stride bytes (64B data + 16B pad)
#define TILEB (128 * ROWB)   // 10240 bytes per matrix tile
#define OFF_AH 0
#define OFF_AL (1 * TILEB)
#define OFF_BH (2 * TILEB)
#define OFF_BL (3 * TILEB)
#define STAGE  (4 * TILEB)   // 40960
#define NSTAGE 2
#define SMEM_TOTAL (NSTAGE * STAGE)  // 81920  -> 2 CTAs/SM

// ---------------- scratch (static device memory) ---------------------------
__device__ float g_bufA[(size_t)TTOK * DIM];                 // fp32 activations (aux/LN out)
__device__ float g_bufC[(size_t)TTOK * DIM];                 // pre-LN y
__device__ float g_H[(size_t)TTOK * ERCOL];
__device__ int   g_maskbuf[TTOK];
__device__ __nv_bfloat16 g_Ah[(size_t)TTOK * DIM];           // activation hi
__device__ __nv_bfloat16 g_Al[(size_t)TTOK * DIM];           // activation lo
__device__ __nv_bfloat16 g_Bh[(size_t)TTOK * DIM];           // new_state hi
__device__ __nv_bfloat16 g_Bl[(size_t)TTOK * DIM];           // new_state lo
__device__ __nv_bfloat16 g_Wh[12ull * DIM * DIM];            // transposed weight hi [N,K]
__device__ __nv_bfloat16 g_Wl[12ull * DIM * DIM];            // transposed weight lo [N,K]

// ---------------- PTX helpers (base sm_103-safe only) -----------------------
__device__ __forceinline__ uint32_t smem_u32(const void* p) {
    uint32_t a;
    asm("{ .reg .u64 t; cvta.to.shared.u64 t, %1; cvt.u32.u64 %0, t; }" : "=r"(a) : "l"(p));
    return a;
}
#define CP_ASYNC16(dst, src) \
    asm volatile("cp.async.cg.shared.global [%0], [%1], 16;" :: "r"(dst), "l"(src) : "memory")
#define CP_COMMIT() asm volatile("cp.async.commit_group;" ::: "memory")
#define CP_WAIT0()  asm volatile("cp.async.wait_group 0;" ::: "memory")
#define LDSM_X4(r0, r1, r2, r3, addr) \
    asm volatile("ldmatrix.sync.aligned.m8n8.x4.shared.b16 {%0,%1,%2,%3}, [%4];" \
                 : "=r"(r0), "=r"(r1), "=r"(r2), "=r"(r3) : "r"(addr))

__device__ __forceinline__ void mma_bf16(float* d, const uint32_t* a, const uint32_t* b) {
    asm volatile(
        "mma.sync.aligned.m16n8k16.row.col.f32.bf16.bf16.f32 "
        "{%0,%1,%2,%3}, {%4,%5,%6,%7}, {%8,%9}, {%0,%1,%2,%3};"
        : "+f"(d[0]), "+f"(d[1]), "+f"(d[2]), "+f"(d[3])
        : "r"(a[0]), "r"(a[1]), "r"(a[2]), "r"(a[3]), "r"(b[0]), "r"(b[1]));
}

__device__ __forceinline__ uint32_t pack_bf16x2(float a, float b) {
    __nv_bfloat16 h0 = __float2bfloat16(a);
    __nv_bfloat16 h1 = __float2bfloat16(b);
    return (uint32_t)__bfloat16_as_ushort(h0) | ((uint32_t)__bfloat16_as_ushort(h1) << 16);
}

// ---------------------------------------------------------------------------
// Input split: X fp32 -> bf16 hi/lo
// ---------------------------------------------------------------------------
__global__ __launch_bounds__(256) void split_x(
    const float* __restrict__ X, __nv_bfloat16* __restrict__ H,
    __nv_bfloat16* __restrict__ L)
{
    const size_t i = ((size_t)blockIdx.x * 256 + threadIdx.x) * 4;
    float4 v = *(const float4*)&X[i];
    float hx = __bfloat162float(__float2bfloat16(v.x));
    float hy = __bfloat162float(__float2bfloat16(v.y));
    float hz = __bfloat162float(__float2bfloat16(v.z));
    float hw = __bfloat162float(__float2bfloat16(v.w));
    uint2 hp = make_uint2(pack_bf16x2(v.x, v.y), pack_bf16x2(v.z, v.w));
    uint2 lp = make_uint2(pack_bf16x2(v.x - hx, v.y - hy), pack_bf16x2(v.z - hz, v.w - hw));
    *(uint2*)&H[i] = hp;
    *(uint2*)&L[i] = lp;
}

// ---------------------------------------------------------------------------
// Weight transpose + bf16 hi/lo split: W[L,K,N] -> Wh/Wl [L,N,K]
// ---------------------------------------------------------------------------
__global__ __launch_bounds__(256) void wsplit_kernel(
    const float* __restrict__ W, __nv_bfloat16* __restrict__ Wh,
    __nv_bfloat16* __restrict__ Wl)
{
    __shared__ float t[32][33];
    const int l = blockIdx.z;
    const float* Wm = W + (size_t)l * DIM * DIM;
    __nv_bfloat16* Whm = Wh + (size_t)l * DIM * DIM;
    __nv_bfloat16* Wlm = Wl + (size_t)l * DIM * DIM;
    const int n0 = blockIdx.x * 32, k0 = blockIdx.y * 32;
    const int tx = threadIdx.x & 31, ty = threadIdx.x >> 5;
    #pragma unroll
    for (int i = 0; i < 4; i++)
        t[ty + i * 8][tx] = Wm[(size_t)(k0 + ty + i * 8) * DIM + n0 + tx];
    __syncthreads();
    #pragma unroll
    for (int i = 0; i < 4; i++) {
        float v = t[tx][ty + i * 8];
        __nv_bfloat16 h = __float2bfloat16(v);
        __nv_bfloat16 lo = __float2bfloat16(v - __bfloat162float(h));
        size_t o = (size_t)(n0 + ty + i * 8) * DIM + k0 + tx;
        Whm[o] = h; Wlm[o] = lo;
    }
}

// ---------------------------------------------------------------------------
// 3xBF16 split GEMM via mma.sync, cp.async 2-stage, 2 CTAs/SM.
// A pre-split bf16 (Ah/Al [M,K]); W pre-split/transposed (Wh/Wl [N,K]).
//   MODE 0: o = sigmoid(acc + bias) * aux * td  -> bf16 hi/lo (Ch/Cl)
//   MODE 1: o = acc + bias + aux                -> fp32 (C)
// CTA 128x128, BK=32, 8 warps (2x4), warp tile 64x32.
// Register-lean inner loop: B frags resident, A frags streamed per mt.
// ---------------------------------------------------------------------------
template<int MODE>
__global__ __launch_bounds__(256, 2) void gemm_mma(
    const __nv_bfloat16* __restrict__ Ah, const __nv_bfloat16* __restrict__ Al,
    const __nv_bfloat16* __restrict__ Wh, const __nv_bfloat16* __restrict__ Wl,
    const float* __restrict__ bias, const float* __restrict__ aux,
    const float* __restrict__ td, float* __restrict__ C,
    __nv_bfloat16* __restrict__ Ch, __nv_bfloat16* __restrict__ Cl)
{
    extern __shared__ char smem[];
    const uint32_t sb0 = smem_u32(smem);
    const int tid  = threadIdx.x;
    const int lane = tid & 31;
    const int wid  = tid >> 5;
    const int m0 = blockIdx.y * BM;
    const int n0 = blockIdx.x * BN;
    const int wm0 = (wid >> 2) * 64;
    const int wn0 = (wid & 3) * 32;

    float acc[4][4][4];
    #pragma unroll
    for (int mt = 0; mt < 4; mt++)
        #pragma unroll
        for (int nt = 0; nt < 4; nt++)
            #pragma unroll
            for (int j = 0; j < 4; j++) acc[mt][nt][j] = 0.f;

    const int cc0 = tid, cc1 = tid + 256;
    const int row0 = cc0 & 127, kb0 = cc0 >> 7;
    const int row1 = cc1 & 127, kb1 = cc1 >> 7;

    auto load_chunk = [&](int c, int st) {
        const int k0c = c * BK;
        const uint32_t sbn = sb0 + st * STAGE;
        {
            uint32_t so = (uint32_t)(row0 * ROWB + kb0 * 16);
            const size_t ga = (size_t)(m0 + row0) * DIM + k0c + kb0 * 8;
            const size_t gb = (size_t)(n0 + row0) * DIM + k0c + kb0 * 8;
            CP_ASYNC16(sbn + OFF_AH + so, Ah + ga);
            CP_ASYNC16(sbn + OFF_AL + so, Al + ga);
            CP_ASYNC16(sbn + OFF_BH + so, Wh + gb);
            CP_ASYNC16(sbn + OFF_BL + so, Wl + gb);
        }
        {
            uint32_t so = (uint32_t)(row1 * ROWB + kb1 * 16);
            const size_t ga = (size_t)(m0 + row1) * DIM + k0c + kb1 * 8;
            const size_t gb = (size_t)(n0 + row1) * DIM + k0c + kb1 * 8;
            CP_ASYNC16(sbn + OFF_AH + so, Ah + ga);
            CP_ASYNC16(sbn + OFF_AL + so, Al + ga);
            CP_ASYNC16(sbn + OFF_BH + so, Wh + gb);
            CP_ASYNC16(sbn + OFF_BL + so, Wl + gb);
        }
        CP_COMMIT();
    };

    // prologue
    load_chunk(0, 0);
    CP_WAIT0();
    __syncthreads();

    const int qr = lane >> 3;
    const int rr = lane & 7;

    for (int c = 0; c < KCH; c++) {
        const uint32_t sbst = sb0 + (c & 1) * STAGE;
        if (c + 1 < KCH) load_chunk(c + 1, (c + 1) & 1);

        #pragma unroll
        for (int kk = 0; kk < 2; kk++) {
            // resident B fragments (16 regs)
            uint32_t bh[4][2], bl[4][2];
            #pragma unroll
            for (int ng = 0; ng < 2; ng++) {
                int brow = wn0 + ng * 16 + rr + (qr >> 1) * 8;
                int bkb  = kk * 2 + (qr & 1);
                uint32_t boff = (uint32_t)(brow * ROWB + bkb * 16);
                uint32_t t0, t1, t2, t3;
                LDSM_X4(t0, t1, t2, t3, sbst + OFF_BH + boff);
                bh[ng * 2][0] = t0; bh[ng * 2][1] = t1;
                bh[ng * 2 + 1][0] = t2; bh[ng * 2 + 1][1] = t3;
                LDSM_X4(t0, t1, t2, t3, sbst + OFF_BL + boff);
                bl[ng * 2][0] = t0; bl[ng * 2][1] = t1;
                bl[ng * 2 + 1][0] = t2; bl[ng * 2 + 1][1] = t3;
            }
            // stream A fragments, 12 MMAs per mt (hh, hl, lh)
            #pragma unroll
            for (int mt = 0; mt < 4; mt++) {
                uint32_t ahf[4], alf[4];
                int arow = wm0 + mt * 16 + rr + (qr & 1) * 8;
                int akb  = kk * 2 + (qr >> 1);
                uint32_t aoff = (uint32_t)(arow * ROWB + akb * 16);
                LDSM_X4(ahf[0], ahf[1], ahf[2], ahf[3], sbst + OFF_AH + aoff);
                LDSM_X4(alf[0], alf[1], alf[2], alf[3], sbst + OFF_AL + aoff);
                #pragma unroll
                for (int nt = 0; nt < 4; nt++) {
                    mma_bf16(acc[mt][nt], ahf, bh[nt]);
                    mma_bf16(acc[mt][nt], ahf, bl[nt]);
                    mma_bf16(acc[mt][nt], alf, bh[nt]);
                }
            }
        }

        CP_WAIT0();
        __syncthreads();
    }

    // -------- epilogue --------
    const int r4 = lane >> 2;
    const int c2 = (lane & 3) * 2;
    #pragma unroll
    for (int mt = 0; mt < 4; mt++) {
        const int rowb = m0 + wm0 + mt * 16 + r4;
        #pragma unroll
        for (int nt = 0; nt < 4; nt++) {
            const int col = n0 + wn0 + nt * 8 + c2;
            float2 bi = *(const float2*)&bias[col];
            float2 tdv;
            if (MODE == 0) tdv = *(const float2*)&td[col];
            #pragma unroll
            for (int half = 0; half < 2; half++) {
                const int rw = rowb + half * 8;
                float2 ax = *(const float2*)&aux[(size_t)rw * DIM + col];
                float v0 = acc[mt][nt][half * 2 + 0] + bi.x;
                float v1 = acc[mt][nt][half * 2 + 1] + bi.y;
                if (MODE == 0) {
                    float g0 = 1.0f / (1.0f + expf(-v0));
                    float g1 = 1.0f / (1.0f + expf(-v1));
                    float o0 = g0 * ax.x * tdv.x;
                    float o1 = g1 * ax.y * tdv.y;
                    float h0 = __bfloat162float(__float2bfloat16(o0));
                    float h1 = __bfloat162float(__float2bfloat16(o1));
                    *(uint32_t*)&Ch[(size_t)rw * DIM + col] = pack_bf16x2(o0, o1);
                    *(uint32_t*)&Cl[(size_t)rw * DIM + col] = pack_bf16x2(o0 - h0, o1 - h1);
                } else {
                    float2 o = make_float2(v0 + ax.x, v1 + ax.y);
                    *(float2*)&C[(size_t)rw * DIM + col] = o;
                }
            }
        }
    }
}

// ---------------------------------------------------------------------------
// Row LayerNorm: fp32 out + bf16 hi/lo out
// ---------------------------------------------------------------------------
__global__ __launch_bounds__(256) void ln_kernel(
    const float* __restrict__ Y, const float* __restrict__ g,
    const float* __restrict__ beta, float* __restrict__ O,
    __nv_bfloat16* __restrict__ Oh, __nv_bfloat16* __restrict__ Ol)
{
    const int row = blockIdx.x;
    const int tid = threadIdx.x;
    float4 v = *(const float4*)&Y[(size_t)row * DIM + tid * 4];
    float s  = v.x + v.y + v.z + v.w;
    float ss = v.x * v.x + v.y * v.y + v.z * v.z + v.w * v.w;

    __shared__ float rs[8], rss[8];
    #pragma unroll
    for (int o = 16; o > 0; o >>= 1) {
        s  += __shfl_down_sync(0xffffffffu, s,  o);
        ss += __shfl_down_sync(0xffffffffu, ss, o);
    }
    if ((tid & 31) == 0) { rs[tid >> 5] = s; rss[tid >> 5] = ss; }
    __syncthreads();
    float ts = 0.f, tss = 0.f;
    #pragma unroll
    for (int w = 0; w < 8; w++) { ts += rs[w]; tss += rss[w]; }
    float mu   = ts * (1.0f / DIM);
    float var  = tss * (1.0f / DIM) - mu * mu;
    float rstd = rsqrtf(var + LN_EPS);

    float4 g4 = *(const float4*)&g[tid * 4];
    float4 b4 = *(const float4*)&beta[tid * 4];
    float4 o4;
    o4.x = (v.x - mu) * rstd * g4.x + b4.x;
    o4.y = (v.y - mu) * rstd * g4.y + b4.y;
    o4.z = (v.z - mu) * rstd * g4.z + b4.z;
    o4.w = (v.w - mu) * rstd * g4.w + b4.w;
    const size_t base = (size_t)row * DIM + tid * 4;
    *(float4*)&O[base] = o4;
    float hx = __bfloat162float(__float2bfloat16(o4.x));
    float hy = __bfloat162float(__float2bfloat16(o4.y));
    float hz = __bfloat162float(__float2bfloat16(o4.z));
    float hw = __bfloat162float(__float2bfloat16(o4.w));
    *(uint2*)&Oh[base] = make_uint2(pack_bf16x2(o4.x, o4.y), pack_bf16x2(o4.z, o4.w));
    *(uint2*)&Ol[base] = make_uint2(pack_bf16x2(o4.x - hx, o4.y - hy),
                                    pack_bf16x2(o4.z - hz, o4.w - hw));
}

// ---------------------------------------------------------------------------
// Gate softmax + top-2 mask
// ---------------------------------------------------------------------------
__global__ __launch_bounds__(128) void gate_kernel(
    const float* __restrict__ Z, const float* __restrict__ W,
    const float* __restrict__ b, float* __restrict__ probs_out,
    int* __restrict__ mask_out)
{
    const int t   = blockIdx.x;
    const int tid = threadIdx.x;
    const float* z = Z + (size_t)t * DIM;
    float4 acc = make_float4(0.f, 0.f, 0.f, 0.f);
    for (int d = tid; d < DIM; d += 128) {
        float zv = z[d];
        float4 w = *(const float4*)&W[d * 4];
        acc.x = fmaf(zv, w.x, acc.x);
        acc.y = fmaf(zv, w.y, acc.y);
        acc.z = fmaf(zv, w.z, acc.z);
        acc.w = fmaf(zv, w.w, acc.w);
    }
    __shared__ float4 red[128];
    red[tid] = acc;
    __syncthreads();
    for (int s = 64; s > 0; s >>= 1) {
        if (tid < s) {
            float4 o = red[tid + s];
            red[tid].x += o.x; red[tid].y += o.y;
            red[tid].z += o.z; red[tid].w += o.w;
        }
        __syncthreads();
    }
    if (tid == 0) {
        float l[4] = { red[0].x + b[0], red[0].y + b[1],
                       red[0].z + b[2], red[0].w + b[3] };
        float mx = l[0];
        #pragma unroll
        for (int e = 1; e < 4; e++) mx = fmaxf(mx, l[e]);
        float ex[4], sum = 0.f;
        #pragma unroll
        for (int e = 0; e < 4; e++) { ex[e] = expf(l[e] - mx); sum += ex[e]; }
        float inv = 1.0f / sum;
        #pragma unroll
        for (int e = 0; e < 4; e++) probs_out[(size_t)t * 4 + e] = ex[e] * inv;
        int i1 = 0;
        #pragma unroll
        for (int e = 1; e < 4; e++) if (l[e] > l[i1]) i1 = e;
        int i2 = -1;
        #pragma unroll
        for (int e = 0; e < 4; e++) {
            if (e == i1) continue;
            if (i2 < 0 || l[e] > l[i2]) i2 = e;
        }
        mask_out[t] = (1 << i1) | (1 << i2);
    }
}

// ---------------------------------------------------------------------------
// H = mask * gelu(Z @ Aflat)
// ---------------------------------------------------------------------------
__global__ __launch_bounds__(256) void h_kernel(
    const float* __restrict__ Z, const float* __restrict__ loraA,
    const int* __restrict__ mask, float* __restrict__ H)
{
    __shared__ float Zs[16][68];
    __shared__ float Afs[16][64];

    const int m0  = blockIdx.x * 64;
    const int tid = threadIdx.x;
    const int ty  = tid >> 4;
    const int tx  = tid & 15;

    float acc[4][4];
    #pragma unroll
    for (int i = 0; i < 4; i++)
        #pragma unroll
        for (int j = 0; j < 4; j++) acc[i][j] = 0.f;

    for (int k0 = 0; k0 < DIM; k0 += 16) {
        {
            int row = tid >> 2;
            int kq  = (tid & 3) << 2;
            float4 v = *(const float4*)&Z[(size_t)(m0 + row) * DIM + k0 + kq];
            Zs[kq + 0][row] = v.x; Zs[kq + 1][row] = v.y;
            Zs[kq + 2][row] = v.z; Zs[kq + 3][row] = v.w;
        }
        {
            int k  = tid >> 4;
            int c4 = (tid & 15) << 2;
            int e  = c4 >> 4;
            int r  = c4 & 15;
            float4 v = *(const float4*)&loraA[(size_t)e * DIM * RANK + (size_t)(k0 + k) * RANK + r];
            *(float4*)&Afs[k][c4] = v;
        }
        __syncthreads();
        #pragma unroll
        for (int k = 0; k < 16; k++) {
            float a[4], b[4];
            *(float4*)&a[0] = *(float4*)&Zs[k][ty * 4];
            *(float4*)&b[0] = *(float4*)&Afs[k][tx * 4];
            #pragma unroll
            for (int i = 0; i < 4; i++)
                #pragma unroll
                for (int j = 0; j < 4; j++)
                    acc[i][j] = fmaf(a[i], b[j], acc[i][j]);
        }
        __syncthreads();
    }

    #pragma unroll
    for (int i = 0; i < 4; i++) {
        int m  = m0 + ty * 4 + i;
        int mk = mask[m];
        #pragma unroll
        for (int j = 0; j < 4; j++) {
            int c = tx * 4 + j;
            int e = c >> 4;
            float x = acc[i][j];
            float h = 0.5f * x * (1.0f + erff(x * 0.70710678118654752f));
            H[(size_t)m * ERCOL + c] = ((mk >> e) & 1) ? h : 0.0f;
        }
    }
}

// ---------------------------------------------------------------------------
// pred = H @ Bflat
// ---------------------------------------------------------------------------
__global__ __launch_bounds__(256) void combine_kernel(
    const float* __restrict__ H, const float* __restrict__ Bf,
    float* __restrict__ O)
{
    const int d  = blockIdx.y * 256 + threadIdx.x;
    const int t0 = blockIdx.x * 16;
    __shared__ float hs[16][64];
    {
        int row = threadIdx.x >> 4;
        int c   = (threadIdx.x & 15) << 2;
        *(float4*)&hs[row][c] = *(const float4*)&H[(size_t)(t0 + row) * ERCOL + c];
    }
    __syncthreads();
    float acc[16];
    #pragma unroll
    for (int i = 0; i < 16; i++) acc[i] = 0.f;
    #pragma unroll 4
    for (int c = 0; c < 64; c++) {
        float bv = Bf[(size_t)c * DIM + d];
        #pragma unroll
        for (int i = 0; i < 16; i++) acc[i] = fmaf(hs[i][c], bv, acc[i]);
    }
    #pragma unroll
    for (int i = 0; i < 16; i++) O[(size_t)(t0 + i) * DIM + d] = acc[i];
}

// ---------------------------------------------------------------------------
extern "C" void kernel_launch(void* const* d_in, const int* in_sizes, int n_in,
                              void* d_out, int out_size)
{
    const float* x_ctx  = (const float*)d_in[0];
    const float* x_tgt  = (const float*)d_in[1];
    const float* P[2][7];
    for (int i = 0; i < 7; i++) { P[0][i] = (const float*)d_in[2 + i];
                                  P[1][i] = (const float*)d_in[9 + i]; }
    const float* gate_W = (const float*)d_in[16];
    const float* gate_b = (const float*)d_in[17];
    const float* lora_A = (const float*)d_in[18];
    const float* lora_B = (const float*)d_in[19];

    float* out      = (float*)d_out;
    float* out_pred = out;
    float* out_gate = out + (size_t)TTOK * DIM;
    float* out_ztgt = out_gate + (size_t)TTOK * NEXP;

    float *bufA, *bufC, *bufH; int* bufM;
    __nv_bfloat16 *Ah, *Al, *Bh, *Bl, *Wh, *Wl;
    cudaGetSymbolAddress((void**)&bufA, g_bufA);
    cudaGetSymbolAddress((void**)&bufC, g_bufC);
    cudaGetSymbolAddress((void**)&bufH, g_H);
    cudaGetSymbolAddress((void**)&Ah,   g_Ah);
    cudaGetSymbolAddress((void**)&Al,   g_Al);
    cudaGetSymbolAddress((void**)&Bh,   g_Bh);
    cudaGetSymbolAddress((void**)&Bl,   g_Bl);
    cudaGetSymbolAddress((void**)&Wh,   g_Wh);
    cudaGetSymbolAddress((void**)&Wl,   g_Wl);
    cudaGetSymbolAddress((void**)&bufM, g_maskbuf);

    cudaFuncSetAttribute(gemm_mma<0>, cudaFuncAttributeMaxDynamicSharedMemorySize, SMEM_TOTAL);
    cudaFuncSetAttribute(gemm_mma<1>, cudaFuncAttributeMaxDynamicSharedMemorySize, SMEM_TOTAL);

    const size_t MM = (size_t)DIM * DIM;
    const dim3 wg(32, 32, 3), wb(256);
    wsplit_kernel<<<wg, wb>>>(P[0][0], Wh + 0 * MM, Wl + 0 * MM);
    wsplit_kernel<<<wg, wb>>>(P[0][3], Wh + 3 * MM, Wl + 3 * MM);
    wsplit_kernel<<<wg, wb>>>(P[1][0], Wh + 6 * MM, Wl + 6 * MM);
    wsplit_kernel<<<wg, wb>>>(P[1][3], Wh + 9 * MM, Wl + 9 * MM);

    const dim3 gg(DIM / BN, TTOK / BM);   // (8, 128)
    const int splitGrid = (TTOK * DIM) / 1024;

    for (int s = 0; s < 2; s++) {
        const float* bi   = P[s][1];
        const float* td   = P[s][2];
        const float* bo   = P[s][4];
        const float* gam  = P[s][5];
        const float* beta = P[s][6];
        const float* xin  = s ? x_tgt : x_ctx;

        split_x<<<splitGrid, 256>>>(xin, Ah, Al);

        for (int l = 0; l < 3; l++) {
            const float* X = (l == 0) ? xin : bufA;   // fp32 aux/residual source
            const size_t wiOff = (size_t)(s * 6 + l) * MM;
            const size_t woOff = (size_t)(s * 6 + 3 + l) * MM;
            gemm_mma<0><<<gg, 256, SMEM_TOTAL>>>(Ah, Al, Wh + wiOff, Wl + wiOff,
                                                 bi + l * DIM, X, td + l * DIM,
                                                 nullptr, Bh, Bl);
            gemm_mma<1><<<gg, 256, SMEM_TOTAL>>>(Bh, Bl, Wh + woOff, Wl + woOff,
                                                 bo + l * DIM, X, nullptr,
                                                 bufC, nullptr, nullptr);
            float* dst = (s == 1 && l == 2) ? out_ztgt : bufA;
            ln_kernel<<<TTOK, 256>>>(bufC, gam + l * DIM, beta + l * DIM, dst, Ah, Al);
        }
        if (s == 0) {
            gate_kernel<<<TTOK, 128>>>(bufA, gate_W, gate_b, out_gate, bufM);
            h_kernel<<<TTOK / 64, 256>>>(bufA, lora_A, bufM, bufH);
            combine_kernel<<<dim3(TTOK / 16, DIM / 256), 256>>>(bufH, lora_B, out_pred);
        }
    }
}